// round 6
// baseline (speedup 1.0000x reference)
#include <cuda_runtime.h>
#include <cuda_bf16.h>
#include <cstdint>

#define NN   882
#define TN   1764
#define MOCC 1024
#define BB   8
#define TT   6
#define KK   24
#define MAXD 32
#define CMAXD 24
#define NW   56          // ceil(1764/32)
#define CN_BLOCKS (BB * MOCC / 8)   // 1024 blocks of 8 warps for cn work

// ---------------- device scratch (no allocations allowed) ----------------
__device__ int   d_row_deg[MOCC];
__device__ int   d_row_cols[MOCC][MAXD];
__device__ int   d_col_cnt[TN];               // atomic counters (self-resetting)
__device__ int   d_col_deg[TN];
__device__ int   d_col_edges[TN][CMAXD];      // edge index = m*MAXD + slot (sorted)
__device__ float d_C[BB][MOCC][MAXD];         // c2v messages (edge state)
__device__ float d_wedge[TT][MOCC][MAXD];     // pre-gathered w_vn on edges
__device__ float d_Gamma[BB][TN];
__device__ float d_pm[BB][TN];                // masked prob for loss
__device__ float d_synsign[BB][MOCC];         // (1 - 2*syn)
__device__ float d_loss[BB][TT];
__device__ unsigned d_wneg[TT][MOCC][NW];     // sign bitmasks of w_vn[0..5]
__device__ unsigned d_wnz [TT][MOCC][NW];
__device__ unsigned d_gneg[BB][NW];           // sign bitmasks of Gamma
__device__ unsigned d_gnz [BB][NW];

// ---------------- accurate fp32 math (flag-independent; rn division) ----
__device__ __forceinline__ float acc_expf(float x) {
    if (x < -87.0f) return 0.0f;
    if (x >  88.0f) return __int_as_float(0x7f800000);
    float kf = rintf(x * 1.4426950408889634f);
    float r  = fmaf(-kf, 0.693359375f, x);
    r = fmaf(kf, 2.12194440e-4f, r);
    float p = 1.9841270e-4f;
    p = fmaf(r, p, 1.3888889e-3f);
    p = fmaf(r, p, 8.3333333e-3f);
    p = fmaf(r, p, 4.1666667e-2f);
    p = fmaf(r, p, 1.6666667e-1f);
    p = fmaf(r, p, 0.5f);
    p = fmaf(r, p, 1.0f);
    p = fmaf(r, p, 1.0f);
    int k = (int)kf;
    float sc = __int_as_float((k + 127) << 23);
    return p * sc;
}

// log for t>0; returns EXACT +-0.0f at t==1.0f (load-bearing for phi semantics)
__device__ __forceinline__ float acc_logf(float t) {
    int ix = __float_as_int(t);
    int e  = ((ix >> 23) & 0xff) - 127;
    float m = __int_as_float((ix & 0x007fffff) | 0x3f800000);   // [1,2)
    if (m > 1.4142135f) { m *= 0.5f; e += 1; }
    float f  = m - 1.0f;
    float s  = __fdiv_rn(f, 2.0f + f);
    float s2 = s * s;
    float p  = fmaf(s2, 0.11111111f, 0.14285714f);
    p = fmaf(s2, p, 0.2f);
    p = fmaf(s2, p, 0.33333333f);
    float lm = fmaf(2.0f * s, s2 * p, 2.0f * s);
    float r  = fmaf((float)e, 0.693359375f, lm);
    r = fmaf((float)e, -2.12194440e-4f, r);
    return r;
}

// XLA / Eigen fast-tanh (f32, FMA variant) — bit-matches jnp.tanh on GPU.
__device__ __forceinline__ float xla_tanhf(float x) {
    float ax = fabsf(x);
    float xc = fminf(fmaxf(x, -7.99881172180175781f), 7.99881172180175781f);
    float x2 = xc * xc;
    float p = -2.76076847742355e-16f;
    p = fmaf(x2, p,  2.00018790482477e-13f);
    p = fmaf(x2, p, -8.60467152213735e-11f);
    p = fmaf(x2, p,  5.12229709037114e-08f);
    p = fmaf(x2, p,  1.48572235717979e-05f);
    p = fmaf(x2, p,  6.37261928875436e-04f);
    p = fmaf(x2, p,  4.89352455891786e-03f);
    float num = xc * p;
    float q = 1.19825839466702e-06f;
    q = fmaf(x2, q, 1.18534705686654e-04f);
    q = fmaf(x2, q, 2.26843463243900e-03f);
    q = fmaf(x2, q, 4.89352518554385e-03f);
    float r = __fdiv_rn(num, q);
    return (ax < 0.0004f) ? x : r;
}

// phi(x) = -log(tanh(x/2)) with the reference's exact tanh quantization.
__device__ __forceinline__ float phi_f(float x) {
    return -acc_logf(xla_tanhf(0.5f * x));
}

// ---------------- loss body (shared by fused + trailing launches) --------
__device__ __forceinline__ void loss_body(const float* __restrict__ Gx,
                                          const float* __restrict__ Gz,
                                          int b, int it,
                                          int tid, float* acc /*smem 2*KK*/) {
    int w = tid >> 5, lane = tid & 31;
    for (int k2 = w; k2 < 2 * KK; k2 += 8) {
        const float* Grow;
        const float* pmrow;
        if (k2 < KK) { Grow = Gx + (size_t)k2 * NN;        pmrow = &d_pm[b][0];  }
        else         { Grow = Gz + (size_t)(k2 - KK) * NN; pmrow = &d_pm[b][NN]; }
        float s = 0.0f;
        for (int n = lane; n < NN; n += 32) s += pmrow[n] * Grow[n];
        for (int o = 16; o; o >>= 1) s += __shfl_xor_sync(0xffffffffu, s, o);
        if (lane == 0) {
            float arg = 1.5707964f * s;                    // fp32 mult like reference
            acc[k2] = fabsf((float)sin((double)arg));      // exact sin on fp32 arg
        }
    }
    __syncthreads();
    if (tid == 0) {
        float t = 0.0f;
        for (int k2 = 0; k2 < 2 * KK; k2++) t += acc[k2];
        d_loss[b][it] = t;
    }
}

// ---------------- kernels ----------------
// Build row adjacency, zero c2v, syndrome parities, atomic column build.
__global__ void k_rows(const float* __restrict__ H,
                       const float* __restrict__ ex, const float* __restrict__ ez) {
    int gw = (blockIdx.x * blockDim.x + threadIdx.x) >> 5;
    int lane = threadIdx.x & 31;
    if (gw >= MOCC) return;
    int m = gw, deg = 0;
    for (int c = 0; c < NW; c++) {
        int j = c * 32 + lane;
        float h = (j < TN) ? H[(size_t)m * TN + j] : 0.0f;
        unsigned bal = __ballot_sync(0xffffffffu, h != 0.0f);
        if (h != 0.0f) {
            int pos = deg + __popc(bal & ((1u << lane) - 1u));
            if (pos < MAXD) d_row_cols[m][pos] = j;
        }
        deg += __popc(bal);
    }
    if (deg > MAXD) deg = MAXD;
    if (lane == 0) d_row_deg[m] = deg;
    for (int b = 0; b < BB; b++) d_C[b][m][lane] = 0.0f;
    __syncwarp();
    bool act = (lane < deg);
    int col = act ? d_row_cols[m][lane] : 0;
    // column lists via atomics (slot == lane); counters pre-zeroed (k_sortcols resets)
    if (act) {
        int pos = atomicAdd(&d_col_cnt[col], 1);
        if (pos < CMAXD) d_col_edges[col][pos] = m * MAXD + lane;
    }
    // syndrome parity per batch
    for (int b = 0; b < BB; b++) {
        float e = 0.0f;
        if (act) e = (col < NN) ? ex[b * NN + col] : ez[b * NN + (col - NN)];
        unsigned bal = __ballot_sync(0xffffffffu, act && (e != 0.0f));
        if (lane == 0) d_synsign[b][m] = (__popc(bal) & 1) ? -1.0f : 1.0f;
    }
}

// Sort each column's edge list ascending (restores reference sum order),
// publish degree, and reset the atomic counters for the next graph replay.
__global__ void k_sortcols() {
    int j = blockIdx.x * blockDim.x + threadIdx.x;
    if (j >= TN) return;
    int cnt = d_col_cnt[j];
    if (cnt > CMAXD) cnt = CMAXD;
    int e[CMAXD];
    for (int k = 0; k < cnt; k++) e[k] = d_col_edges[j][k];
    for (int i = 1; i < cnt; i++) {
        int key = e[i], p = i - 1;
        while (p >= 0 && e[p] > key) { e[p + 1] = e[p]; p--; }
        e[p + 1] = key;
    }
    for (int k = 0; k < cnt; k++) d_col_edges[j][k] = e[k];
    d_col_deg[j] = cnt;
    d_col_cnt[j] = 0;
}

// Phase A (blocks < MASK_BLOCKS): thread-per-mask-word, float4 loads.
// Phase B: thread-per-edge gather of w_vn values into d_wedge.
#define MASK_WORDS (TT * MOCC * NW)                  // 344064
#define MASK_BLOCKS ((MASK_WORDS + 255) / 256)       // 1344
#define GATH_BLOCKS (TT * MOCC * MAXD / 256)         // 768
__global__ void k_wprep(const float* __restrict__ w_vn) {
    if (blockIdx.x < MASK_BLOCKS) {
        int t = blockIdx.x * 256 + threadIdx.x;
        if (t >= MASK_WORDS) return;
        int row = t / NW, c = t % NW;
        const float* base = w_vn + (size_t)row * TN + c * 32;
        int nvec = (c == NW - 1) ? 1 : 8;            // last word: only 4 floats
        unsigned neg = 0, nz = 0;
        for (int v = 0; v < nvec; v++) {
            float4 f = reinterpret_cast<const float4*>(base)[v];
            int k = v * 4;
            neg |= ((f.x < 0.0f) ? 1u : 0u) << k;
            neg |= ((f.y < 0.0f) ? 1u : 0u) << (k + 1);
            neg |= ((f.z < 0.0f) ? 1u : 0u) << (k + 2);
            neg |= ((f.w < 0.0f) ? 1u : 0u) << (k + 3);
            nz  |= ((f.x != 0.0f) ? 1u : 0u) << k;
            nz  |= ((f.y != 0.0f) ? 1u : 0u) << (k + 1);
            nz  |= ((f.z != 0.0f) ? 1u : 0u) << (k + 2);
            nz  |= ((f.w != 0.0f) ? 1u : 0u) << (k + 3);
        }
        (&d_wneg[0][0][0])[(size_t)row * NW + c] = neg;
        (&d_wnz [0][0][0])[(size_t)row * NW + c] = nz;
    } else {
        int t = (blockIdx.x - MASK_BLOCKS) * 256 + threadIdx.x;
        int slot = t & (MAXD - 1);
        int m    = (t >> 5) & (MOCC - 1);
        int it   = t >> 15;
        float w = 0.0f;
        if (slot < d_row_deg[m]) {
            int col = d_row_cols[m][slot];
            w = w_vn[((size_t)it * MOCC + m) * TN + col];
        }
        d_wedge[it][m][slot] = w;
    }
}

// CN update for iteration `it`; blocks >= CN_BLOCKS compute loss(it-1).
__global__ void k_cn(const float* __restrict__ w_cn,
                     const float* __restrict__ ep, const float* __restrict__ w_llr,
                     const float* __restrict__ Gx, const float* __restrict__ Gz, int it) {
    if (blockIdx.x >= CN_BLOCKS) {
        __shared__ float acc[2 * KK];
        if (it > 0) loss_body(Gx, Gz, blockIdx.x - CN_BLOCKS, it - 1, threadIdx.x, acc);
        return;
    }
    int gw = (blockIdx.x * blockDim.x + threadIdx.x) >> 5;
    int lane = threadIdx.x & 31;
    int b = gw >> 10, m = gw & 1023;

    float gconst = 0.0f;
    if (it == 0) {
        float e = ep[0];
        gconst = acc_logf(__fdiv_rn(1.0f - e, e)) * w_llr[0];
    }

    // dense sign-product parity over all 1764 columns via bitmasks
    const unsigned* wneg = d_wneg[it][m];
    const unsigned* wnz  = d_wnz [it][m];
    int cnt = 0;
    if (it == 0) {
        unsigned GN = (gconst < 0.0f) ? 0xffffffffu : 0u;
        unsigned GZ = (gconst != 0.0f) ? 0xffffffffu : 0u;   // tail killed by wnz
        for (int c = lane; c < NW; c += 32)
            cnt += __popc((GN ^ wneg[c]) & GZ & wnz[c]);
    } else {
        const unsigned* gneg = d_gneg[b];
        const unsigned* gnz  = d_gnz [b];
        for (int c = lane; c < NW; c += 32)
            cnt += __popc((gneg[c] ^ wneg[c]) & gnz[c] & wnz[c]);
    }
    for (int o = 16; o; o >>= 1) cnt += __shfl_xor_sync(0xffffffffu, cnt, o);
    int parity = cnt & 1;

    int deg = d_row_deg[m];
    bool act = (lane < deg);
    float V = 0.0f, phi = 0.0f;
    int corr = 0;
    if (act) {
        int j = d_row_cols[m][lane];
        float G = (it == 0) ? gconst : d_Gamma[b][j];
        float Cold = d_C[b][m][lane];
        float w = d_wedge[it][m][lane];
        float x = G - Cold;
        x = fminf(fmaxf(x, -30.0f), 30.0f);
        V = x * w;
        int pneg = (((G < 0.0f) != (w < 0.0f)) && (G != 0.0f) && (w != 0.0f)) ? 1 : 0;
        int vneg = (V < 0.0f) ? 1 : 0;
        corr = pneg ^ vneg;                  // swap dense-formula sign for true v2c sign
        if (V != 0.0f) phi = phi_f(fabsf(V));
    }
    unsigned cb = __ballot_sync(0xffffffffu, corr);
    parity ^= (__popc(cb) & 1);

    float A = phi;
    for (int o = 16; o; o >>= 1) A += __shfl_xor_sync(0xffffffffu, A, o);

    if (act) {
        float P = parity ? -1.0f : 1.0f;
        float first = (V < 0.0f) ? -P : P;   // P / sign_k  (sign in {-1,+1})
        float s2 = A - phi;
        float second = (s2 != 0.0f) ? phi_f(s2) : 0.0f;
        float out = ((first * second) * d_synsign[b][m]) * w_cn[it * MOCC + m];
        d_C[b][m][lane] = out;
    }
}

__global__ void k_vn(const float* __restrict__ ep, const float* __restrict__ w_llr,
                     const float* __restrict__ ex, const float* __restrict__ ez, int ip1) {
    int j = blockIdx.x * blockDim.x + threadIdx.x;
    int b = blockIdx.y;
    int lane = threadIdx.x & 31;
    bool in = (j < TN);
    float g = 0.0f;
    if (in) {
        float e = ep[0];
        float llr = acc_logf(__fdiv_rn(1.0f - e, e));
        float sum = 0.0f;
        int cd = d_col_deg[j];
        const float* Cb = &d_C[b][0][0];
        for (int k = 0; k < cd; k++) sum += Cb[d_col_edges[j][k]];
        g = llr * w_llr[ip1] + sum;
        d_Gamma[b][j] = g;
        float mask = (j < NN) ? ex[b * NN + j] : ez[b * NN + (j - NN)];
        float pmv = 0.0f;
        if (mask == 1.0f) pmv = __fdiv_rn(1.0f, 1.0f + acc_expf(g));  // sigmoid(-Gamma)
        d_pm[b][j] = pmv;
    }
    unsigned bneg = __ballot_sync(0xffffffffu, in && (g < 0.0f));
    unsigned bnz  = __ballot_sync(0xffffffffu, in && (g != 0.0f));
    if (lane == 0 && (j >> 5) < NW) { d_gneg[b][j >> 5] = bneg; d_gnz[b][j >> 5] = bnz; }
}

__global__ void k_loss_last(const float* __restrict__ Gx, const float* __restrict__ Gz) {
    __shared__ float acc[2 * KK];
    loss_body(Gx, Gz, blockIdx.x, TT - 1, threadIdx.x, acc);
}

__global__ void k_final(float* __restrict__ out) {
    if (threadIdx.x == 0 && blockIdx.x == 0) {
        float tot = 0.0f;
        for (int b = 0; b < BB; b++) {
            float best = d_loss[b][0];
            int bi = 0;
            for (int i = 1; i < TT; i++)
                if (d_loss[b][i] < best) { best = d_loss[b][i]; bi = i; }
            float cs = 0.0f;
            for (int i = 0; i <= bi; i++) cs += d_loss[b][i];
            tot += __fdiv_rn(cs, (float)(bi + 1));
        }
        out[0] = tot * 0.125f;
    }
}

// ---------------- launch ----------------
extern "C" void kernel_launch(void* const* d_in, const int* in_sizes, int n_in,
                              void* d_out, int out_size) {
    const float* ex    = (const float*)d_in[0];
    const float* ez    = (const float*)d_in[1];
    const float* ep    = (const float*)d_in[2];
    const float* H     = (const float*)d_in[3];
    const float* Gx    = (const float*)d_in[6];
    const float* Gz    = (const float*)d_in[7];
    const float* w_vn  = (const float*)d_in[8];
    const float* w_llr = (const float*)d_in[9];
    const float* w_cn  = (const float*)d_in[10];
    float* out = (float*)d_out;

    k_rows    <<<MOCC / 8, 256>>>(H, ex, ez);
    k_sortcols<<<(TN + 255) / 256, 256>>>();
    k_wprep   <<<MASK_BLOCKS + GATH_BLOCKS, 256>>>(w_vn);

    dim3 gv((TN + 255) / 256, BB);
    for (int i = 0; i < TT; i++) {
        k_cn<<<CN_BLOCKS + BB, 256>>>(w_cn, ep, w_llr, Gx, Gz, i);
        k_vn<<<gv, 256>>>(ep, w_llr, ex, ez, i + 1);
    }
    k_loss_last<<<BB, 256>>>(Gx, Gz);
    k_final<<<1, 32>>>(out);
}

// round 7
// speedup vs baseline: 1.1914x; 1.1914x over previous
#include <cuda_runtime.h>
#include <cuda_bf16.h>
#include <cstdint>

#define NN   882
#define TN   1764
#define MOCC 1024
#define BB   8
#define TT   6
#define KK   24
#define MAXD 32
#define CMAXD 24
#define PADCD 16
#define NW   56          // ceil(1764/32)
#define CN_BLOCKS (BB * MOCC / 8)   // 1024 blocks of 8 warps for cn work
#define DUMMY_EDGE (MOCC * MAXD)    // points at always-zero padding row of d_C

// ---------------- device scratch (no allocations allowed) ----------------
__device__ int   d_row_deg[MOCC];
__device__ int   d_row_cols[MOCC][MAXD];
__device__ int   d_col_cnt[TN];               // atomic counters (self-resetting)
__device__ int   d_col_deg[TN];
__device__ int   d_col_edges[TN][CMAXD];      // edge index = m*MAXD + slot (sorted, padded)
__device__ float d_C[BB][MOCC + 1][MAXD];     // c2v messages; row MOCC = permanent zeros
__device__ float d_wedge[TT][MOCC][MAXD];     // pre-gathered w_vn on edges
__device__ float d_Gamma[BB][TN];
__device__ float d_pm[BB][TN];                // masked prob for loss
__device__ float d_synsign[BB][MOCC];         // (1 - 2*syn)
__device__ float d_loss[BB][TT];
__device__ unsigned d_wneg[TT][MOCC][NW];     // sign bitmasks of w_vn[0..5]
__device__ unsigned d_wnz [TT][MOCC][NW];
__device__ unsigned d_gneg[BB][NW];           // sign bitmasks of Gamma
__device__ unsigned d_gnz [BB][NW];

// ---------------- accurate fp32 math (flag-independent; rn division) ----
__device__ __forceinline__ float acc_expf(float x) {
    if (x < -87.0f) return 0.0f;
    if (x >  88.0f) return __int_as_float(0x7f800000);
    float kf = rintf(x * 1.4426950408889634f);
    float r  = fmaf(-kf, 0.693359375f, x);
    r = fmaf(kf, 2.12194440e-4f, r);
    float p = 1.9841270e-4f;
    p = fmaf(r, p, 1.3888889e-3f);
    p = fmaf(r, p, 8.3333333e-3f);
    p = fmaf(r, p, 4.1666667e-2f);
    p = fmaf(r, p, 1.6666667e-1f);
    p = fmaf(r, p, 0.5f);
    p = fmaf(r, p, 1.0f);
    p = fmaf(r, p, 1.0f);
    int k = (int)kf;
    float sc = __int_as_float((k + 127) << 23);
    return p * sc;
}

// log for t>0; returns EXACT +-0.0f at t==1.0f (load-bearing for phi semantics)
__device__ __forceinline__ float acc_logf(float t) {
    int ix = __float_as_int(t);
    int e  = ((ix >> 23) & 0xff) - 127;
    float m = __int_as_float((ix & 0x007fffff) | 0x3f800000);   // [1,2)
    if (m > 1.4142135f) { m *= 0.5f; e += 1; }
    float f  = m - 1.0f;
    float s  = __fdiv_rn(f, 2.0f + f);
    float s2 = s * s;
    float p  = fmaf(s2, 0.11111111f, 0.14285714f);
    p = fmaf(s2, p, 0.2f);
    p = fmaf(s2, p, 0.33333333f);
    float lm = fmaf(2.0f * s, s2 * p, 2.0f * s);
    float r  = fmaf((float)e, 0.693359375f, lm);
    r = fmaf((float)e, -2.12194440e-4f, r);
    return r;
}

// XLA / Eigen fast-tanh (f32, FMA variant) — bit-matches jnp.tanh on GPU.
__device__ __forceinline__ float xla_tanhf(float x) {
    float ax = fabsf(x);
    float xc = fminf(fmaxf(x, -7.99881172180175781f), 7.99881172180175781f);
    float x2 = xc * xc;
    float p = -2.76076847742355e-16f;
    p = fmaf(x2, p,  2.00018790482477e-13f);
    p = fmaf(x2, p, -8.60467152213735e-11f);
    p = fmaf(x2, p,  5.12229709037114e-08f);
    p = fmaf(x2, p,  1.48572235717979e-05f);
    p = fmaf(x2, p,  6.37261928875436e-04f);
    p = fmaf(x2, p,  4.89352455891786e-03f);
    float num = xc * p;
    float q = 1.19825839466702e-06f;
    q = fmaf(x2, q, 1.18534705686654e-04f);
    q = fmaf(x2, q, 2.26843463243900e-03f);
    q = fmaf(x2, q, 4.89352518554385e-03f);
    float r = __fdiv_rn(num, q);
    return (ax < 0.0004f) ? x : r;
}

// phi(x) = -log(tanh(x/2)) with the reference's exact tanh quantization.
__device__ __forceinline__ float phi_f(float x) {
    return -acc_logf(xla_tanhf(0.5f * x));
}

// |sin(argf)| accurate to ~1e-12 absolute: double-double pi reduction +
// odd Taylor to r^15 on [-pi/2, pi/2]. |k| <= ~300 here, so reduction exact
// to ~1e-13. 13 fp64 ops vs ~50 in libdevice sin.
__device__ __forceinline__ float abs_sin_acc(float argf) {
    double a = (double)argf;
    double k = rint(a * 0.31830988618379067154);       // 1/pi
    double r = fma(-k, 3.141592653589793116, a);
    r = fma(-k, 1.2246467991473531772e-16, r);
    double r2 = r * r;
    double p = -7.6471637318198164759e-13;             // -1/15!
    p = fma(r2, p,  1.6059043836821614599e-10);        //  1/13!
    p = fma(r2, p, -2.5052108385441718775e-08);        // -1/11!
    p = fma(r2, p,  2.7557319223985890653e-06);        //  1/9!
    p = fma(r2, p, -1.9841269841269841253e-04);        // -1/7!
    p = fma(r2, p,  8.3333333333333332177e-03);        //  1/5!
    p = fma(r2, p, -1.6666666666666666574e-01);        // -1/3!
    p = fma(r2, p,  1.0);
    return fabsf((float)(r * p));
}

// ---------------- loss body: dots, then all 48 sins in parallel ----------
__device__ __forceinline__ void loss_body(const float* __restrict__ Gx,
                                          const float* __restrict__ Gz,
                                          int b, int it,
                                          int tid, float* acc /*smem 2*KK*/) {
    int w = tid >> 5, lane = tid & 31;
    for (int k2 = w; k2 < 2 * KK; k2 += 8) {
        const float* Grow;
        const float* pmrow;
        if (k2 < KK) { Grow = Gx + (size_t)k2 * NN;        pmrow = &d_pm[b][0];  }
        else         { Grow = Gz + (size_t)(k2 - KK) * NN; pmrow = &d_pm[b][NN]; }
        float s = 0.0f;
        for (int n = lane; n < NN; n += 32) s += pmrow[n] * Grow[n];
        for (int o = 16; o; o >>= 1) s += __shfl_xor_sync(0xffffffffu, s, o);
        if (lane == 0) acc[k2] = s;
    }
    __syncthreads();
    if (tid < 2 * KK) acc[tid] = abs_sin_acc(1.5707964f * acc[tid]);  // parallel sins
    __syncthreads();
    if (tid == 0) {
        float t = 0.0f;
        for (int k2 = 0; k2 < 2 * KK; k2++) t += acc[k2];
        d_loss[b][it] = t;
    }
}

// ---------------- kernels ----------------
// Build row adjacency, zero c2v, syndrome parities, atomic column build.
__global__ void k_rows(const float* __restrict__ H,
                       const float* __restrict__ ex, const float* __restrict__ ez) {
    int gw = (blockIdx.x * blockDim.x + threadIdx.x) >> 5;
    int lane = threadIdx.x & 31;
    if (gw >= MOCC) return;
    int m = gw, deg = 0;
    for (int c = 0; c < NW; c++) {
        int j = c * 32 + lane;
        float h = (j < TN) ? H[(size_t)m * TN + j] : 0.0f;
        unsigned bal = __ballot_sync(0xffffffffu, h != 0.0f);
        if (h != 0.0f) {
            int pos = deg + __popc(bal & ((1u << lane) - 1u));
            if (pos < MAXD) d_row_cols[m][pos] = j;
        }
        deg += __popc(bal);
    }
    if (deg > MAXD) deg = MAXD;
    if (lane == 0) d_row_deg[m] = deg;
    for (int b = 0; b < BB; b++) d_C[b][m][lane] = 0.0f;
    __syncwarp();
    bool act = (lane < deg);
    int col = act ? d_row_cols[m][lane] : 0;
    if (act) {
        int pos = atomicAdd(&d_col_cnt[col], 1);
        if (pos < CMAXD) d_col_edges[col][pos] = m * MAXD + lane;
    }
    for (int b = 0; b < BB; b++) {
        float e = 0.0f;
        if (act) e = (col < NN) ? ex[b * NN + col] : ez[b * NN + (col - NN)];
        unsigned bal = __ballot_sync(0xffffffffu, act && (e != 0.0f));
        if (lane == 0) d_synsign[b][m] = (__popc(bal) & 1) ? -1.0f : 1.0f;
    }
}

// Phase A: thread-per-mask-word, float4 loads. Phase B: thread-per-edge
// gather into d_wedge. Phase C: sort + pad column lists, reset counters.
#define MASK_WORDS (TT * MOCC * NW)                  // 344064
#define MASK_BLOCKS ((MASK_WORDS + 255) / 256)       // 1344
#define GATH_BLOCKS (TT * MOCC * MAXD / 256)         // 768
#define SORT_BLOCKS ((TN + 255) / 256)               // 7
__global__ void k_wprep(const float* __restrict__ w_vn) {
    if (blockIdx.x < MASK_BLOCKS) {
        int t = blockIdx.x * 256 + threadIdx.x;
        if (t >= MASK_WORDS) return;
        int row = t / NW, c = t % NW;
        const float* base = w_vn + (size_t)row * TN + c * 32;
        int nvec = (c == NW - 1) ? 1 : 8;            // last word: only 4 floats
        unsigned neg = 0, nz = 0;
        for (int v = 0; v < nvec; v++) {
            float4 f = reinterpret_cast<const float4*>(base)[v];
            int k = v * 4;
            neg |= ((f.x < 0.0f) ? 1u : 0u) << k;
            neg |= ((f.y < 0.0f) ? 1u : 0u) << (k + 1);
            neg |= ((f.z < 0.0f) ? 1u : 0u) << (k + 2);
            neg |= ((f.w < 0.0f) ? 1u : 0u) << (k + 3);
            nz  |= ((f.x != 0.0f) ? 1u : 0u) << k;
            nz  |= ((f.y != 0.0f) ? 1u : 0u) << (k + 1);
            nz  |= ((f.z != 0.0f) ? 1u : 0u) << (k + 2);
            nz  |= ((f.w != 0.0f) ? 1u : 0u) << (k + 3);
        }
        (&d_wneg[0][0][0])[(size_t)row * NW + c] = neg;
        (&d_wnz [0][0][0])[(size_t)row * NW + c] = nz;
    } else if (blockIdx.x < MASK_BLOCKS + GATH_BLOCKS) {
        int t = (blockIdx.x - MASK_BLOCKS) * 256 + threadIdx.x;
        int slot = t & (MAXD - 1);
        int m    = (t >> 5) & (MOCC - 1);
        int it   = t >> 15;
        float w = 0.0f;
        if (slot < d_row_deg[m]) {
            int col = d_row_cols[m][slot];
            w = w_vn[((size_t)it * MOCC + m) * TN + col];
        }
        d_wedge[it][m][slot] = w;
    } else {
        int j = (blockIdx.x - MASK_BLOCKS - GATH_BLOCKS) * 256 + threadIdx.x;
        if (j >= TN) return;
        int cnt = d_col_cnt[j];
        if (cnt > CMAXD) cnt = CMAXD;
        int e[CMAXD];
        for (int k = 0; k < cnt; k++) e[k] = d_col_edges[j][k];
        for (int i = 1; i < cnt; i++) {                 // ascending m order
            int key = e[i], p = i - 1;
            while (p >= 0 && e[p] > key) { e[p + 1] = e[p]; p--; }
            e[p + 1] = key;
        }
        for (int k = 0; k < cnt; k++) d_col_edges[j][k] = e[k];
        for (int k = cnt; k < PADCD; k++) d_col_edges[j][k] = DUMMY_EDGE;
        d_col_deg[j] = cnt;
        d_col_cnt[j] = 0;                               // reset for next replay
    }
}

// CN update for iteration `it`; blocks >= CN_BLOCKS compute loss(it-1).
__global__ void k_cn(const float* __restrict__ w_cn,
                     const float* __restrict__ ep, const float* __restrict__ w_llr,
                     const float* __restrict__ Gx, const float* __restrict__ Gz, int it) {
    if (blockIdx.x >= CN_BLOCKS) {
        __shared__ float acc[2 * KK];
        if (it > 0) loss_body(Gx, Gz, blockIdx.x - CN_BLOCKS, it - 1, threadIdx.x, acc);
        return;
    }
    int gw = (blockIdx.x * blockDim.x + threadIdx.x) >> 5;
    int lane = threadIdx.x & 31;
    int b = gw >> 10, m = gw & 1023;

    float gconst = 0.0f;
    if (it == 0) {
        float e = ep[0];
        gconst = acc_logf(__fdiv_rn(1.0f - e, e)) * w_llr[0];
    }

    // dense sign-product parity over all 1764 columns via bitmasks
    const unsigned* wneg = d_wneg[it][m];
    const unsigned* wnz  = d_wnz [it][m];
    int cnt = 0;
    if (it == 0) {
        unsigned GN = (gconst < 0.0f) ? 0xffffffffu : 0u;
        unsigned GZ = (gconst != 0.0f) ? 0xffffffffu : 0u;   // tail killed by wnz
        for (int c = lane; c < NW; c += 32)
            cnt += __popc((GN ^ wneg[c]) & GZ & wnz[c]);
    } else {
        const unsigned* gneg = d_gneg[b];
        const unsigned* gnz  = d_gnz [b];
        for (int c = lane; c < NW; c += 32)
            cnt += __popc((gneg[c] ^ wneg[c]) & gnz[c] & wnz[c]);
    }
    for (int o = 16; o; o >>= 1) cnt += __shfl_xor_sync(0xffffffffu, cnt, o);
    int parity = cnt & 1;

    int deg = d_row_deg[m];
    bool act = (lane < deg);
    float V = 0.0f, phi = 0.0f;
    int corr = 0;
    if (act) {
        int j = d_row_cols[m][lane];
        float G = (it == 0) ? gconst : d_Gamma[b][j];
        float Cold = d_C[b][m][lane];
        float w = d_wedge[it][m][lane];
        float x = G - Cold;
        x = fminf(fmaxf(x, -30.0f), 30.0f);
        V = x * w;
        int pneg = (((G < 0.0f) != (w < 0.0f)) && (G != 0.0f) && (w != 0.0f)) ? 1 : 0;
        int vneg = (V < 0.0f) ? 1 : 0;
        corr = pneg ^ vneg;                  // swap dense-formula sign for true v2c sign
        if (V != 0.0f) phi = phi_f(fabsf(V));
    }
    unsigned cb = __ballot_sync(0xffffffffu, corr);
    parity ^= (__popc(cb) & 1);

    float A = phi;
    for (int o = 16; o; o >>= 1) A += __shfl_xor_sync(0xffffffffu, A, o);

    if (act) {
        float P = parity ? -1.0f : 1.0f;
        float first = (V < 0.0f) ? -P : P;   // P / sign_k  (sign in {-1,+1})
        float s2 = A - phi;
        float second = (s2 != 0.0f) ? phi_f(s2) : 0.0f;
        float out = ((first * second) * d_synsign[b][m]) * w_cn[it * MOCC + m];
        d_C[b][m][lane] = out;
    }
}

__global__ void k_vn(const float* __restrict__ ep, const float* __restrict__ w_llr,
                     const float* __restrict__ ex, const float* __restrict__ ez, int ip1) {
    int j = blockIdx.x * blockDim.x + threadIdx.x;
    int b = blockIdx.y;
    int lane = threadIdx.x & 31;
    bool in = (j < TN);
    float g = 0.0f;
    if (in) {
        float e = ep[0];
        float llr = acc_logf(__fdiv_rn(1.0f - e, e));
        const float* Cb = &d_C[b][0][0];
        float sum = 0.0f;
        #pragma unroll
        for (int k = 0; k < PADCD; k++) sum += Cb[d_col_edges[j][k]];  // padded: MLP 16
        int cd = d_col_deg[j];
        if (cd > PADCD)
            for (int k = PADCD; k < cd; k++) sum += Cb[d_col_edges[j][k]];
        g = llr * w_llr[ip1] + sum;
        d_Gamma[b][j] = g;
        float mask = (j < NN) ? ex[b * NN + j] : ez[b * NN + (j - NN)];
        float pmv = 0.0f;
        if (mask == 1.0f) pmv = __fdiv_rn(1.0f, 1.0f + acc_expf(g));  // sigmoid(-Gamma)
        d_pm[b][j] = pmv;
    }
    unsigned bneg = __ballot_sync(0xffffffffu, in && (g < 0.0f));
    unsigned bnz  = __ballot_sync(0xffffffffu, in && (g != 0.0f));
    if (lane == 0 && (j >> 5) < NW) { d_gneg[b][j >> 5] = bneg; d_gnz[b][j >> 5] = bnz; }
}

__global__ void k_loss_last(const float* __restrict__ Gx, const float* __restrict__ Gz) {
    __shared__ float acc[2 * KK];
    loss_body(Gx, Gz, blockIdx.x, TT - 1, threadIdx.x, acc);
}

__global__ void k_final(float* __restrict__ out) {
    if (threadIdx.x == 0 && blockIdx.x == 0) {
        float tot = 0.0f;
        for (int b = 0; b < BB; b++) {
            float best = d_loss[b][0];
            int bi = 0;
            for (int i = 1; i < TT; i++)
                if (d_loss[b][i] < best) { best = d_loss[b][i]; bi = i; }
            float cs = 0.0f;
            for (int i = 0; i <= bi; i++) cs += d_loss[b][i];
            tot += __fdiv_rn(cs, (float)(bi + 1));
        }
        out[0] = tot * 0.125f;
    }
}

// ---------------- launch ----------------
extern "C" void kernel_launch(void* const* d_in, const int* in_sizes, int n_in,
                              void* d_out, int out_size) {
    const float* ex    = (const float*)d_in[0];
    const float* ez    = (const float*)d_in[1];
    const float* ep    = (const float*)d_in[2];
    const float* H     = (const float*)d_in[3];
    const float* Gx    = (const float*)d_in[6];
    const float* Gz    = (const float*)d_in[7];
    const float* w_vn  = (const float*)d_in[8];
    const float* w_llr = (const float*)d_in[9];
    const float* w_cn  = (const float*)d_in[10];
    float* out = (float*)d_out;

    k_rows <<<MOCC / 8, 256>>>(H, ex, ez);
    k_wprep<<<MASK_BLOCKS + GATH_BLOCKS + SORT_BLOCKS, 256>>>(w_vn);

    dim3 gv((TN + 127) / 128, BB);
    for (int i = 0; i < TT; i++) {
        k_cn<<<CN_BLOCKS + BB, 256>>>(w_cn, ep, w_llr, Gx, Gz, i);
        k_vn<<<gv, 128>>>(ep, w_llr, ex, ez, i + 1);
    }
    k_loss_last<<<BB, 256>>>(Gx, Gz);
    k_final<<<1, 32>>>(out);
}